// round 16
// baseline (speedup 1.0000x reference)
#include <cuda_runtime.h>
#include <cuda_bf16.h>
#include <cstdint>

// Problem constants: N=4096, L_V=64, H=512, D=256
constexpr int NB   = 4096;
constexpr int LV   = 64;
constexpr int HD   = 512;
constexpr int DD   = 256;
constexpr int K1   = 3 * DD;   // 768
constexpr int KTOT = K1 + HD;  // 1280

// GEMM tiling: CTA tile 128x128, K stepped by 16 (one m16n8k16 per step)
constexpr int BM = 128, BN = 128, BKS = 16;
constexpr int NIT = KTOT / BKS;                    // 80
constexpr int GEMM_CTAS  = (NB / BM) * (HD / BN);  // 128
constexpr int TOTAL_CTAS = 304;                    // 2 per SM on 152 SMs

// Copy pool
constexpr int ROWS_TOTAL = NB * LV;                // 262144 rows of 512 floats
constexpr int NUM_GRABS  = ROWS_TOTAL / 32;        // 8192

// Conversion geometry (prep kernel, 128 converter CTAs)
constexpr int CONV_CTAS     = 128;
constexpr int XSLICE_ROWS   = NB / CONV_CTAS;      // 32 rows per converter
constexpr int XSLICE_CHUNKS = XSLICE_ROWS * (KTOT / 4);  // 10240 float4 chunks
constexpr int WCOLS         = HD / CONV_CTAS;      // 4 W columns per converter

__device__ int g_copy_ctr;        // zero-init; spans BOTH kernels; self-reset
__device__ int g_conv_done;       // converters arrived (prep stop flag)
__device__ int g_done;            // fused-kernel completion counter
__device__ __align__(16) __nv_bfloat16 g_xhi[NB * KTOT];  // X hi plane (10MB)
__device__ __align__(16) __nv_bfloat16 g_xlo[NB * KTOT];  // X lo plane
__device__ __align__(16) __nv_bfloat16 g_whi[HD * KTOT];  // W^T hi (k-major)
__device__ __align__(16) __nv_bfloat16 g_wlo[HD * KTOT];  // W^T lo

// ---------------- PTX helpers ----------------
__device__ __forceinline__ uint32_t s2u(const void* p) {
    uint32_t a;
    asm("{ .reg .u64 t; cvta.to.shared.u64 t, %1; cvt.u32.u64 %0, t; }"
        : "=r"(a) : "l"(p));
    return a;
}
__device__ __forceinline__ void cp16(uint32_t dst, const void* src) {
    asm volatile("cp.async.cg.shared.global [%0], [%1], 16;" :: "r"(dst), "l"(src));
}
__device__ __forceinline__ void cp_commit() {
    asm volatile("cp.async.commit_group;");
}
template <int N>
__device__ __forceinline__ void cp_wait() {
    asm volatile("cp.async.wait_group %0;" :: "n"(N));
}
__device__ __forceinline__ void ldsm4(uint32_t* r, uint32_t addr) {
    asm volatile("ldmatrix.sync.aligned.m8n8.x4.shared.b16 {%0,%1,%2,%3}, [%4];"
                 : "=r"(r[0]), "=r"(r[1]), "=r"(r[2]), "=r"(r[3]) : "r"(addr));
}
__device__ __forceinline__ void mma16816(float* d, const uint32_t* a,
                                         const uint32_t* b) {
    asm volatile(
        "mma.sync.aligned.m16n8k16.row.col.f32.bf16.bf16.f32 "
        "{%0,%1,%2,%3}, {%4,%5,%6,%7}, {%8,%9}, {%0,%1,%2,%3};"
        : "+f"(d[0]), "+f"(d[1]), "+f"(d[2]), "+f"(d[3])
        : "r"(a[0]), "r"(a[1]), "r"(a[2]), "r"(a[3]), "r"(b[0]), "r"(b[1]));
}
__device__ __forceinline__ float4 ldcs(const float4* p) {
    float4 v;
    asm volatile("ld.global.cs.v4.f32 {%0,%1,%2,%3}, [%4];"
                 : "=f"(v.x), "=f"(v.y), "=f"(v.z), "=f"(v.w) : "l"(p));
    return v;
}
__device__ __forceinline__ void stcs(float4* p, float4 v) {
    asm volatile("st.global.cs.v4.f32 [%0], {%1,%2,%3,%4};"
                 :: "l"(p), "f"(v.x), "f"(v.y), "f"(v.z), "f"(v.w) : "memory");
}
__device__ __forceinline__ uint32_t pack_hi2(float a, float b,
                                             float& ra, float& rb) {
    __nv_bfloat16 h0 = __float2bfloat16_rn(a);
    __nv_bfloat16 h1 = __float2bfloat16_rn(b);
    ra = a - __bfloat162float(h0);
    rb = b - __bfloat162float(h1);
    return ((uint32_t)*(uint16_t*)&h1 << 16) | *(uint16_t*)&h0;
}
__device__ __forceinline__ uint32_t pack_bf2(float a, float b) {
    __nv_bfloat162 t = __floats2bfloat162_rn(a, b);
    return *reinterpret_cast<uint32_t*>(&t);
}

// --------------------------------------------------------------------------
// Copy grab: copy rows [c*32, c*32+32) skipping the GEMM-owned scatter row.
// --------------------------------------------------------------------------
__device__ __forceinline__ void copy_grab(const float4* __restrict__ src,
                                          float4* __restrict__ dst,
                                          const int* __restrict__ veh_idx,
                                          int c, int lane)
{
    const int r0   = c * 32;                // same n for the whole grab
    const int n    = r0 >> 6;
    const int skip = veh_idx[n] & (LV - 1);
    const int l0   = r0 & 63;

    for (int g = 0; g < 8; g++) {
        float4 v[16];
        size_t base = (size_t)(r0 + g * 4) * (HD / 4) + lane;
        #pragma unroll
        for (int rr = 0; rr < 4; rr++) {
            if (l0 + g * 4 + rr == skip) continue;     // dead row: no read
            #pragma unroll
            for (int q = 0; q < 4; q++)
                v[rr * 4 + q] = ldcs(src + base + rr * 128 + q * 32);
        }
        #pragma unroll
        for (int rr = 0; rr < 4; rr++) {
            if (l0 + g * 4 + rr == skip) continue;     // GEMM writes this row
            #pragma unroll
            for (int q = 0; q < 4; q++)
                stcs(dst + base + rr * 128 + q * 32, v[rr * 4 + q]);
        }
    }
}

// Unbounded copy pool (fused kernel): run until the counter is exhausted.
__device__ __forceinline__ void copy_role(const float4* __restrict__ src,
                                          float4* __restrict__ dst,
                                          const int* __restrict__ veh_idx,
                                          int lane)
{
    for (;;) {
        int c;
        if (lane == 0) c = atomicAdd(&g_copy_ctr, 1);
        c = __shfl_sync(0xffffffffu, c, 0);
        if (c >= NUM_GRABS) return;
        copy_grab(src, dst, veh_idx, c, lane);
    }
}

// Bounded copy pool (prep kernel): stop once all converters have arrived.
// Check-before-claim: a claimed grab is always completed.
__device__ __forceinline__ void copy_role_bounded(const float4* __restrict__ src,
                                                  float4* __restrict__ dst,
                                                  const int* __restrict__ veh_idx,
                                                  int lane)
{
    for (;;) {
        int c;
        if (lane == 0) {
            c = (*(volatile int*)&g_conv_done >= CONV_CTAS)
                    ? NUM_GRABS : atomicAdd(&g_copy_ctr, 1);
        }
        c = __shfl_sync(0xffffffffu, c, 0);
        if (c >= NUM_GRABS) return;
        copy_grab(src, dst, veh_idx, c, lane);
    }
}

// --------------------------------------------------------------------------
// prep kernel (grid 304):
//  bids [0,128): convert X slice (32 rows) + W sliver (4 cols) -> planes,
//                then arrive on g_conv_done.
//  bids [128,304): copy pool from t=0, bounded by conversion completion —
//                the passthrough copy makes progress during the prep window.
// --------------------------------------------------------------------------
__global__ __launch_bounds__(256)
void prep_kernel(const float* __restrict__ memory,
                 const int*   __restrict__ veh_idx,
                 const float* __restrict__ veh_repr,
                 const float* __restrict__ cust_repr,
                 const float* __restrict__ edge_emb,
                 const float* __restrict__ W_in,
                 const float* __restrict__ W_h,
                 float* __restrict__ out)
{
    const int tid  = threadIdx.x;
    const int bid  = blockIdx.x;
    const int lane = tid & 31;

    if (bid >= CONV_CTAS) {
        copy_role_bounded((const float4*)memory, (float4*)out, veh_idx, lane);
        return;
    }

    // ---- X slice conversion: rows [bid*32, bid*32+32) ----
    {
        const int slice_m = bid * XSLICE_ROWS;
        for (int g = 0; g < XSLICE_CHUNKS / (256 * 4); g++) {   // 10 groups
            float4 v[4];
            int    eidx[4];
            #pragma unroll
            for (int u = 0; u < 4; u++) {
                const int c = (g * 4 + u) * 256 + tid;
                const int m = slice_m + c / (KTOT / 4);
                const int k = (c % (KTOT / 4)) * 4;
                eidx[u] = m * KTOT + k;
                const float* src;
                if (k < DD)          src = veh_repr  + (size_t)m * DD + k;
                else if (k < 2 * DD) src = cust_repr + (size_t)m * DD + (k - DD);
                else if (k < K1)     src = edge_emb  + (size_t)m * DD + (k - 2 * DD);
                else {
                    const int idx = veh_idx[m] & (LV - 1);
                    src = memory + ((size_t)m * LV + idx) * HD + (k - K1);
                }
                v[u] = *(const float4*)src;          // 4 loads batched (MLP=4)
            }
            #pragma unroll
            for (int u = 0; u < 4; u++) {
                float r0, r1, r2, r3;
                uint2 ph, pl;
                ph.x = pack_hi2(v[u].x, v[u].y, r0, r1);
                ph.y = pack_hi2(v[u].z, v[u].w, r2, r3);
                pl.x = pack_bf2(r0, r1);
                pl.y = pack_bf2(r2, r3);
                *(uint2*)&g_xhi[eidx[u]] = ph;
                *(uint2*)&g_xlo[eidx[u]] = pl;
            }
        }
    }

    // ---- W sliver: 4 columns x 1280 k, via smem [1280][4] ----
    {
        __shared__ float tile[KTOT][WCOLS];          // 20KB
        const int nw0 = bid * WCOLS;                 // this CTA's 4 columns
        #pragma unroll
        for (int i = 0; i < 5; i++) {
            const int k = tid + i * 256;             // 0..1279
            const float* Wrow = (k < K1) ? (W_in + (size_t)k * HD)
                                         : (W_h + (size_t)(k - K1) * HD);
            *(float4*)tile[k] = *(const float4*)&Wrow[nw0];
        }
        __syncthreads();
        #pragma unroll
        for (int i = 0; i < 10; i++) {
            const int idx = i * 256 + tid;           // 0..2559
            const int n   = idx / (KTOT / 2);        // 0..3
            const int kk  = (idx % (KTOT / 2)) * 2;  // even k
            float r0, r1;
            const uint32_t hi = pack_hi2(tile[kk][n], tile[kk + 1][n], r0, r1);
            const uint32_t lo = pack_bf2(r0, r1);
            const size_t off = (size_t)(nw0 + n) * KTOT + kk;
            *(uint32_t*)&g_whi[off] = hi;
            *(uint32_t*)&g_wlo[off] = lo;
        }
    }

    __syncthreads();
    if (tid == 0) {
        __threadfence();
        atomicAdd(&g_conv_done, 1);      // releases prep's copy CTAs to exit
    }
}

// --------------------------------------------------------------------------
// Fused kernel (R13-proven). bids [0,128): mma.sync bf16 GEMM with 3-term
// hi/lo split, 3-stage cp.async pipeline; epilogue scatters tanh(acc+bias)
// into out[n, veh_idx[n], :]. All CTAs end in the copy pool (counter
// continues from the prep kernel). Last CTA out resets all counters.
// --------------------------------------------------------------------------
__global__ __launch_bounds__(256, 2)
void fused_kernel(const float* __restrict__ memory,
                  const int*   __restrict__ veh_idx,
                  const float* __restrict__ b_in,
                  const float* __restrict__ b_h,
                  float* __restrict__ out)
{
    // 3 stages x 16KB: per stage: xhi[128][16] | xlo | whi[128][16] | wlo
    __shared__ __align__(128) char raw[49152];

    const int tid  = threadIdx.x;
    const int bid  = blockIdx.x;
    const int lane = tid & 31;

    if (bid < GEMM_CTAS) {
        const int block_m = (bid >> 2) * BM;
        const int block_n = (bid & 3) * BN;
        const int w  = tid >> 5;
        const int wm = w >> 1;          // 0..3 -> rows wm*32
        const int wn = w & 1;           // 0..1 -> cols wn*64
        const uint32_t sbase = s2u(raw);

        // cp.async mapping: thread -> (row 0..127, 16B half)
        const int row  = tid >> 1;
        const int half = tid & 1;
        const uint32_t dxy = (uint32_t)(row * 32 + half * 16);
        const size_t gx = (size_t)(block_m + row) * KTOT + half * 8;
        const size_t gw = (size_t)(block_n + row) * KTOT + half * 8;

        auto issue = [&](int it, int buf) {
            const int k0 = it * BKS;
            const uint32_t sb = sbase + (uint32_t)buf * 16384;
            cp16(sb + dxy,          g_xhi + gx + k0);
            cp16(sb + 4096 + dxy,   g_xlo + gx + k0);
            cp16(sb + 8192 + dxy,   g_whi + gw + k0);
            cp16(sb + 12288 + dxy,  g_wlo + gw + k0);
            cp_commit();
        };

        uint32_t aoff[2];
        #pragma unroll
        for (int i = 0; i < 2; i++) {
            const int r = wm * 32 + i * 16 + (lane & 7) + ((lane >> 3) & 1) * 8;
            aoff[i] = (uint32_t)(r * 32 + ((lane >> 4) & 1) * 16);
        }
        uint32_t boff[4];
        #pragma unroll
        for (int p = 0; p < 4; p++) {
            const int r = wn * 64 + p * 16 + (lane & 7) + ((lane >> 4) & 1) * 8;
            boff[p] = (uint32_t)(r * 32 + ((lane >> 3) & 1) * 16);
        }

        float d[2][8][4];
        #pragma unroll
        for (int i = 0; i < 2; i++)
            #pragma unroll
            for (int j = 0; j < 8; j++)
                #pragma unroll
                for (int q = 0; q < 4; q++) d[i][j][q] = 0.0f;

        issue(0, 0);
        issue(1, 1);

        int buf = 0, nbuf = 2;
        for (int it = 0; it < NIT; it++) {
            if (it + 2 < NIT) cp_wait<1>(); else cp_wait<0>();
            __syncthreads();
            if (it + 2 < NIT) issue(it + 2, nbuf);

            const uint32_t sb = sbase + (uint32_t)buf * 16384;
            uint32_t ah[2][4], al[2][4], bb[8][2];
            ldsm4(ah[0], sb + aoff[0]);
            ldsm4(ah[1], sb + aoff[1]);
            ldsm4(al[0], sb + 4096 + aoff[0]);
            ldsm4(al[1], sb + 4096 + aoff[1]);
            #pragma unroll
            for (int p = 0; p < 4; p++) {
                uint32_t r[4];
                ldsm4(r, sb + 8192 + boff[p]);      // W hi
                bb[2 * p][0] = r[0]; bb[2 * p][1] = r[1];
                bb[2 * p + 1][0] = r[2]; bb[2 * p + 1][1] = r[3];
            }
            #pragma unroll
            for (int i = 0; i < 2; i++)
                #pragma unroll
                for (int j = 0; j < 8; j++) {
                    mma16816(d[i][j], ah[i], bb[j]);   // hi*hi
                    mma16816(d[i][j], al[i], bb[j]);   // lo*hi
                }
            #pragma unroll
            for (int p = 0; p < 4; p++) {
                uint32_t r[4];
                ldsm4(r, sb + 12288 + boff[p]);     // W lo
                bb[2 * p][0] = r[0]; bb[2 * p][1] = r[1];
                bb[2 * p + 1][0] = r[2]; bb[2 * p + 1][1] = r[3];
            }
            #pragma unroll
            for (int i = 0; i < 2; i++)
                #pragma unroll
                for (int j = 0; j < 8; j++)
                    mma16816(d[i][j], ah[i], bb[j]);   // hi*lo

            buf  = (buf  == 2) ? 0 : buf + 1;
            nbuf = (nbuf == 2) ? 0 : nbuf + 1;
        }

        // epilogue: bias + tanh -> scatter directly to out[n, idx[n], :]
        float2 bias[8];
        #pragma unroll
        for (int j = 0; j < 8; j++) {
            const int col = block_n + wn * 64 + j * 8 + (lane & 3) * 2;
            bias[j].x = b_in[col] + b_h[col];
            bias[j].y = b_in[col + 1] + b_h[col + 1];
        }
        #pragma unroll
        for (int i = 0; i < 2; i++) {
            const int m0 = block_m + wm * 32 + i * 16 + (lane >> 2);
            const int m1 = m0 + 8;
            const size_t base0 = ((size_t)m0 * LV + (veh_idx[m0] & (LV - 1))) * HD;
            const size_t base1 = ((size_t)m1 * LV + (veh_idx[m1] & (LV - 1))) * HD;
            #pragma unroll
            for (int j = 0; j < 8; j++) {
                const int col = block_n + wn * 64 + j * 8 + (lane & 3) * 2;
                float2 v0, v1;
                v0.x = tanhf(d[i][j][0] + bias[j].x);
                v0.y = tanhf(d[i][j][1] + bias[j].y);
                v1.x = tanhf(d[i][j][2] + bias[j].x);
                v1.y = tanhf(d[i][j][3] + bias[j].y);
                *(float2*)&out[base0 + col] = v0;
                *(float2*)&out[base1 + col] = v1;
            }
        }
    }

    // Copy pool — resumes from the counter value the prep kernel reached.
    copy_role((const float4*)memory, (float4*)out, veh_idx, lane);

    // Last CTA out resets all counters for the next graph replay.
    __syncthreads();
    if (tid == 0) {
        const int dcount = atomicAdd(&g_done, 1);
        if (dcount == TOTAL_CTAS - 1) {
            g_copy_ctr  = 0;
            g_conv_done = 0;
            __threadfence();
            g_done = 0;
        }
    }
}

extern "C" void kernel_launch(void* const* d_in, const int* in_sizes, int n_in,
                              void* d_out, int out_size)
{
    const float* memory    = (const float*)d_in[0];
    const int*   veh_idx   = (const int*)d_in[1];
    const float* veh_repr  = (const float*)d_in[2];
    const float* cust_repr = (const float*)d_in[3];
    const float* edge_emb  = (const float*)d_in[4];
    const float* W_in      = (const float*)d_in[5];
    const float* b_in      = (const float*)d_in[6];
    const float* W_h       = (const float*)d_in[7];
    const float* b_h       = (const float*)d_in[8];
    float*       out       = (float*)d_out;

    prep_kernel<<<TOTAL_CTAS, 256>>>(memory, veh_idx, veh_repr, cust_repr,
                                     edge_emb, W_in, W_h, out);
    fused_kernel<<<TOTAL_CTAS, 256>>>(memory, veh_idx, b_in, b_h, out);
}

// round 17
// speedup vs baseline: 1.1876x; 1.1876x over previous
#include <cuda_runtime.h>
#include <cuda_bf16.h>
#include <cstdint>

// Problem constants: N=4096, L_V=64, H=512, D=256
constexpr int NB   = 4096;
constexpr int LV   = 64;
constexpr int HD   = 512;
constexpr int DD   = 256;
constexpr int K1   = 3 * DD;   // 768
constexpr int KTOT = K1 + HD;  // 1280

// GEMM tiling: CTA tile 128x128, K stepped by 16 (one m16n8k16 per step)
constexpr int BM = 128, BN = 128, BKS = 16;
constexpr int NIT = KTOT / BKS;                    // 80
constexpr int GEMM_CTAS  = (NB / BM) * (HD / BN);  // 128
constexpr int TOTAL_CTAS = 304;                    // 2 per SM on 152 SMs (all wave-1)

// Copy pool
constexpr int ROWS_TOTAL = NB * LV;                // 262144 rows of 512 floats
constexpr int NUM_GRABS  = ROWS_TOTAL / 32;        // 8192

// Phase-A conversion geometry
constexpr int XCHUNKS  = NB * KTOT / 4;            // 1,310,720 float4 chunks
constexpr int XGROUP   = 256 * 4;                  // chunks per CTA-group pass
constexpr int NGROUPS  = XCHUNKS / XGROUP;         // 1280
constexpr int WCOLS    = HD / GEMM_CTAS;           // 4 W columns per GEMM CTA

__device__ int g_copy_ctr;        // zero-init; self-reset each replay
__device__ int g_conv_done;       // phase-A arrivals (global barrier)
__device__ int g_done;            // kernel completion counter
__device__ __align__(16) __nv_bfloat16 g_xhi[NB * KTOT];  // X hi plane (10MB)
__device__ __align__(16) __nv_bfloat16 g_xlo[NB * KTOT];  // X lo plane
__device__ __align__(16) __nv_bfloat16 g_whi[HD * KTOT];  // W^T hi (k-major)
__device__ __align__(16) __nv_bfloat16 g_wlo[HD * KTOT];  // W^T lo

// ---------------- PTX helpers ----------------
__device__ __forceinline__ uint32_t s2u(const void* p) {
    uint32_t a;
    asm("{ .reg .u64 t; cvta.to.shared.u64 t, %1; cvt.u32.u64 %0, t; }"
        : "=r"(a) : "l"(p));
    return a;
}
__device__ __forceinline__ void cp16(uint32_t dst, const void* src) {
    asm volatile("cp.async.cg.shared.global [%0], [%1], 16;" :: "r"(dst), "l"(src));
}
__device__ __forceinline__ void cp_commit() {
    asm volatile("cp.async.commit_group;");
}
template <int N>
__device__ __forceinline__ void cp_wait() {
    asm volatile("cp.async.wait_group %0;" :: "n"(N));
}
__device__ __forceinline__ void ldsm4(uint32_t* r, uint32_t addr) {
    asm volatile("ldmatrix.sync.aligned.m8n8.x4.shared.b16 {%0,%1,%2,%3}, [%4];"
                 : "=r"(r[0]), "=r"(r[1]), "=r"(r[2]), "=r"(r[3]) : "r"(addr));
}
__device__ __forceinline__ void mma16816(float* d, const uint32_t* a,
                                         const uint32_t* b) {
    asm volatile(
        "mma.sync.aligned.m16n8k16.row.col.f32.bf16.bf16.f32 "
        "{%0,%1,%2,%3}, {%4,%5,%6,%7}, {%8,%9}, {%0,%1,%2,%3};"
        : "+f"(d[0]), "+f"(d[1]), "+f"(d[2]), "+f"(d[3])
        : "r"(a[0]), "r"(a[1]), "r"(a[2]), "r"(a[3]), "r"(b[0]), "r"(b[1]));
}
__device__ __forceinline__ float4 ldcs(const float4* p) {
    float4 v;
    asm volatile("ld.global.cs.v4.f32 {%0,%1,%2,%3}, [%4];"
                 : "=f"(v.x), "=f"(v.y), "=f"(v.z), "=f"(v.w) : "l"(p));
    return v;
}
__device__ __forceinline__ void stcs(float4* p, float4 v) {
    asm volatile("st.global.cs.v4.f32 [%0], {%1,%2,%3,%4};"
                 :: "l"(p), "f"(v.x), "f"(v.y), "f"(v.z), "f"(v.w) : "memory");
}
__device__ __forceinline__ uint32_t pack_hi2(float a, float b,
                                             float& ra, float& rb) {
    __nv_bfloat16 h0 = __float2bfloat16_rn(a);
    __nv_bfloat16 h1 = __float2bfloat16_rn(b);
    ra = a - __bfloat162float(h0);
    rb = b - __bfloat162float(h1);
    return ((uint32_t)*(uint16_t*)&h1 << 16) | *(uint16_t*)&h0;
}
__device__ __forceinline__ uint32_t pack_bf2(float a, float b) {
    __nv_bfloat162 t = __floats2bfloat162_rn(a, b);
    return *reinterpret_cast<uint32_t*>(&t);
}

// --------------------------------------------------------------------------
// Copy pool: work-stealing passthrough. Skips both load and store of the row
// each batch's GEMM scatters. Warp grabs 32 rows; up to 16 LDG.128 in flight.
// --------------------------------------------------------------------------
__device__ __forceinline__ void copy_role(const float4* __restrict__ src,
                                          float4* __restrict__ dst,
                                          const int* __restrict__ veh_idx,
                                          int lane)
{
    for (;;) {
        int c;
        if (lane == 0) c = atomicAdd(&g_copy_ctr, 1);
        c = __shfl_sync(0xffffffffu, c, 0);
        if (c >= NUM_GRABS) return;

        const int r0   = c * 32;            // same n for the whole grab
        const int n    = r0 >> 6;
        const int skip = veh_idx[n] & (LV - 1);
        const int l0   = r0 & 63;

        for (int g = 0; g < 8; g++) {
            float4 v[16];
            size_t base = (size_t)(r0 + g * 4) * (HD / 4) + lane;
            #pragma unroll
            for (int rr = 0; rr < 4; rr++) {
                if (l0 + g * 4 + rr == skip) continue;   // dead row: no read
                #pragma unroll
                for (int q = 0; q < 4; q++)
                    v[rr * 4 + q] = ldcs(src + base + rr * 128 + q * 32);
            }
            #pragma unroll
            for (int rr = 0; rr < 4; rr++) {
                if (l0 + g * 4 + rr == skip) continue;   // GEMM writes this row
                #pragma unroll
                for (int q = 0; q < 4; q++)
                    stcs(dst + base + rr * 128 + q * 32, v[rr * 4 + q]);
            }
        }
    }
}

// --------------------------------------------------------------------------
// Single phase-gated kernel.
//  Phase A (ALL 304 CTAs, copy gated off — conversion owns the fabric):
//    X -> bf16 hi/lo planes, grid-strided groups across all CTAs;
//    W -> transposed hi/lo slivers (4 cols each) on bids [0,128).
//    Global barrier via g_conv_done (all CTAs co-resident in wave 1).
//  Phase B: bids [0,128) run the R13-proven mma.sync GEMM then join the
//    copy pool; bids [128,304) go straight to the copy pool.
//  Last CTA out resets all counters for the next graph replay.
// --------------------------------------------------------------------------
__global__ __launch_bounds__(256, 2)
void fused_kernel(const float* __restrict__ memory,
                  const int*   __restrict__ veh_idx,
                  const float* __restrict__ veh_repr,
                  const float* __restrict__ cust_repr,
                  const float* __restrict__ edge_emb,
                  const float* __restrict__ W_in,
                  const float* __restrict__ W_h,
                  const float* __restrict__ b_in,
                  const float* __restrict__ b_h,
                  float* __restrict__ out)
{
    // GEMM: 3 stages x 16KB. Phase A reuses it as the W staging tile (20KB).
    __shared__ __align__(128) char raw[49152];

    const int tid  = threadIdx.x;
    const int bid  = blockIdx.x;
    const int lane = tid & 31;

    // ===================== Phase A: conversions ============================
    // X: grid-strided groups; reversed bid so the remainder groups land on
    // high-bid (copy-only) CTAs, balancing against the W work on bids<128.
    for (int g = TOTAL_CTAS - 1 - bid; g < NGROUPS; g += TOTAL_CTAS) {
        float4 v[4];
        int    eidx[4];
        #pragma unroll
        for (int u = 0; u < 4; u++) {
            const int c = g * XGROUP + u * 256 + tid;
            const int e = c * 4;                 // float index; 16B chunk never
            const int m = e / KTOT;              // crosses a 256-float boundary
            const int k = e % KTOT;
            eidx[u] = e;
            const float* src;
            if (k < DD)          src = veh_repr  + (size_t)m * DD + k;
            else if (k < 2 * DD) src = cust_repr + (size_t)m * DD + (k - DD);
            else if (k < K1)     src = edge_emb  + (size_t)m * DD + (k - 2 * DD);
            else {
                const int idx = veh_idx[m] & (LV - 1);
                src = memory + ((size_t)m * LV + idx) * HD + (k - K1);
            }
            v[u] = *(const float4*)src;          // 4 loads batched (MLP=4)
        }
        #pragma unroll
        for (int u = 0; u < 4; u++) {
            float r0, r1, r2, r3;
            uint2 ph, pl;
            ph.x = pack_hi2(v[u].x, v[u].y, r0, r1);
            ph.y = pack_hi2(v[u].z, v[u].w, r2, r3);
            pl.x = pack_bf2(r0, r1);
            pl.y = pack_bf2(r2, r3);
            *(uint2*)&g_xhi[eidx[u]] = ph;
            *(uint2*)&g_xlo[eidx[u]] = pl;
        }
    }

    // W sliver: 4 columns x 1280 k on bids [0,128), via smem [1280][4]
    if (bid < GEMM_CTAS) {
        float (*tile)[WCOLS] = (float (*)[WCOLS])raw;    // 20KB in raw
        const int nw0 = bid * WCOLS;
        #pragma unroll
        for (int i = 0; i < 5; i++) {
            const int k = tid + i * 256;                 // 0..1279
            const float* Wrow = (k < K1) ? (W_in + (size_t)k * HD)
                                         : (W_h + (size_t)(k - K1) * HD);
            *(float4*)tile[k] = *(const float4*)&Wrow[nw0];
        }
        __syncthreads();
        #pragma unroll
        for (int i = 0; i < 10; i++) {
            const int idx = i * 256 + tid;               // 0..2559
            const int n   = idx / (KTOT / 2);            // 0..3
            const int kk  = (idx % (KTOT / 2)) * 2;      // even k
            float r0, r1;
            const uint32_t hi = pack_hi2(tile[kk][n], tile[kk + 1][n], r0, r1);
            const uint32_t lo = pack_bf2(r0, r1);
            const size_t off = (size_t)(nw0 + n) * KTOT + kk;
            *(uint32_t*)&g_whi[off] = hi;
            *(uint32_t*)&g_wlo[off] = lo;
        }
    }

    // ----- global barrier: all 304 CTAs (co-resident -> deadlock-free) -----
    __syncthreads();
    if (tid == 0) {
        __threadfence();                         // release plane writes
        atomicAdd(&g_conv_done, 1);
        while (atomicAdd(&g_conv_done, 0) < TOTAL_CTAS) __nanosleep(100);
    }
    __syncthreads();
    // cp.async.cg below bypasses L1 -> reads L2-coherent plane data.

    // ===================== Phase B: GEMM + copy ============================
    if (bid < GEMM_CTAS) {
        const int block_m = (bid >> 2) * BM;
        const int block_n = (bid & 3) * BN;
        const int w  = tid >> 5;
        const int wm = w >> 1;          // 0..3 -> rows wm*32
        const int wn = w & 1;           // 0..1 -> cols wn*64
        const uint32_t sbase = s2u(raw);

        // cp.async mapping: thread -> (row 0..127, 16B half)
        const int row  = tid >> 1;
        const int half = tid & 1;
        const uint32_t dxy = (uint32_t)(row * 32 + half * 16);
        const size_t gx = (size_t)(block_m + row) * KTOT + half * 8;
        const size_t gw = (size_t)(block_n + row) * KTOT + half * 8;

        auto issue = [&](int it, int buf) {
            const int k0 = it * BKS;
            const uint32_t sb = sbase + (uint32_t)buf * 16384;
            cp16(sb + dxy,          g_xhi + gx + k0);
            cp16(sb + 4096 + dxy,   g_xlo + gx + k0);
            cp16(sb + 8192 + dxy,   g_whi + gw + k0);
            cp16(sb + 12288 + dxy,  g_wlo + gw + k0);
            cp_commit();
        };

        uint32_t aoff[2];
        #pragma unroll
        for (int i = 0; i < 2; i++) {
            const int r = wm * 32 + i * 16 + (lane & 7) + ((lane >> 3) & 1) * 8;
            aoff[i] = (uint32_t)(r * 32 + ((lane >> 4) & 1) * 16);
        }
        uint32_t boff[4];
        #pragma unroll
        for (int p = 0; p < 4; p++) {
            const int r = wn * 64 + p * 16 + (lane & 7) + ((lane >> 4) & 1) * 8;
            boff[p] = (uint32_t)(r * 32 + ((lane >> 3) & 1) * 16);
        }

        float d[2][8][4];
        #pragma unroll
        for (int i = 0; i < 2; i++)
            #pragma unroll
            for (int j = 0; j < 8; j++)
                #pragma unroll
                for (int q = 0; q < 4; q++) d[i][j][q] = 0.0f;

        issue(0, 0);
        issue(1, 1);

        int buf = 0, nbuf = 2;
        for (int it = 0; it < NIT; it++) {
            if (it + 2 < NIT) cp_wait<1>(); else cp_wait<0>();
            __syncthreads();
            if (it + 2 < NIT) issue(it + 2, nbuf);

            const uint32_t sb = sbase + (uint32_t)buf * 16384;
            uint32_t ah[2][4], al[2][4], bb[8][2];
            ldsm4(ah[0], sb + aoff[0]);
            ldsm4(ah[1], sb + aoff[1]);
            ldsm4(al[0], sb + 4096 + aoff[0]);
            ldsm4(al[1], sb + 4096 + aoff[1]);
            #pragma unroll
            for (int p = 0; p < 4; p++) {
                uint32_t r[4];
                ldsm4(r, sb + 8192 + boff[p]);      // W hi
                bb[2 * p][0] = r[0]; bb[2 * p][1] = r[1];
                bb[2 * p + 1][0] = r[2]; bb[2 * p + 1][1] = r[3];
            }
            #pragma unroll
            for (int i = 0; i < 2; i++)
                #pragma unroll
                for (int j = 0; j < 8; j++) {
                    mma16816(d[i][j], ah[i], bb[j]);   // hi*hi
                    mma16816(d[i][j], al[i], bb[j]);   // lo*hi
                }
            #pragma unroll
            for (int p = 0; p < 4; p++) {
                uint32_t r[4];
                ldsm4(r, sb + 12288 + boff[p]);     // W lo
                bb[2 * p][0] = r[0]; bb[2 * p][1] = r[1];
                bb[2 * p + 1][0] = r[2]; bb[2 * p + 1][1] = r[3];
            }
            #pragma unroll
            for (int i = 0; i < 2; i++)
                #pragma unroll
                for (int j = 0; j < 8; j++)
                    mma16816(d[i][j], ah[i], bb[j]);   // hi*lo

            buf  = (buf  == 2) ? 0 : buf + 1;
            nbuf = (nbuf == 2) ? 0 : nbuf + 1;
        }

        // epilogue: bias + tanh -> scatter directly to out[n, idx[n], :]
        float2 bias[8];
        #pragma unroll
        for (int j = 0; j < 8; j++) {
            const int col = block_n + wn * 64 + j * 8 + (lane & 3) * 2;
            bias[j].x = b_in[col] + b_h[col];
            bias[j].y = b_in[col + 1] + b_h[col + 1];
        }
        #pragma unroll
        for (int i = 0; i < 2; i++) {
            const int m0 = block_m + wm * 32 + i * 16 + (lane >> 2);
            const int m1 = m0 + 8;
            const size_t base0 = ((size_t)m0 * LV + (veh_idx[m0] & (LV - 1))) * HD;
            const size_t base1 = ((size_t)m1 * LV + (veh_idx[m1] & (LV - 1))) * HD;
            #pragma unroll
            for (int j = 0; j < 8; j++) {
                const int col = block_n + wn * 64 + j * 8 + (lane & 3) * 2;
                float2 v0, v1;
                v0.x = tanhf(d[i][j][0] + bias[j].x);
                v0.y = tanhf(d[i][j][1] + bias[j].y);
                v1.x = tanhf(d[i][j][2] + bias[j].x);
                v1.y = tanhf(d[i][j][3] + bias[j].y);
                *(float2*)&out[base0 + col] = v0;
                *(float2*)&out[base1 + col] = v1;
            }
        }
    }

    // Copy pool (copy-only CTAs arrive right after the barrier).
    copy_role((const float4*)memory, (float4*)out, veh_idx, lane);

    // Last CTA out resets all counters for the next graph replay.
    __syncthreads();
    if (tid == 0) {
        const int dcount = atomicAdd(&g_done, 1);
        if (dcount == TOTAL_CTAS - 1) {
            g_copy_ctr  = 0;
            g_conv_done = 0;
            __threadfence();
            g_done = 0;
        }
    }
}

extern "C" void kernel_launch(void* const* d_in, const int* in_sizes, int n_in,
                              void* d_out, int out_size)
{
    const float* memory    = (const float*)d_in[0];
    const int*   veh_idx   = (const int*)d_in[1];
    const float* veh_repr  = (const float*)d_in[2];
    const float* cust_repr = (const float*)d_in[3];
    const float* edge_emb  = (const float*)d_in[4];
    const float* W_in      = (const float*)d_in[5];
    const float* b_in      = (const float*)d_in[6];
    const float* W_h       = (const float*)d_in[7];
    const float* b_h       = (const float*)d_in[8];
    float*       out       = (float*)d_out;

    fused_kernel<<<TOTAL_CTAS, 256>>>(memory, veh_idx, veh_repr, cust_repr,
                                      edge_emb, W_in, W_h, b_in, b_h, out);
}